// round 17
// baseline (speedup 1.0000x reference)
#include <cuda_runtime.h>
#include <cuda_bf16.h>
#include <cstdint>

// Sizes (fixed): B=64, T=1024, D=512, H=256, 4H=1024, two directions.

__device__ float G_buf [(size_t)65536 * 2048];        // [m = b*1024 + t][j]
__device__ float Gt_buf[(size_t)1024 * 2048 * 64];    // [t][j][b]
__device__ float Hhist [(size_t)2 * 1024 * 16384];    // [dir][t][q*64 + b] (out only)
__device__ __nv_bfloat16 Hbf[(size_t)2 * 1024 * 64 * 512]; // [dir][t][b][hi k|lo k]
__device__ unsigned g_arrive[2][4][16][32];           // [dir][bgroup][qslice][pad]
__device__ __align__(16) __nv_bfloat16 Abuf[(size_t)65536 * 1536]; // [m][hi|hi|lo]
__device__ __align__(16) __nv_bfloat16 Wbuf[(size_t)2048 * 1536];  // [j][Whi|Wlo|Whi]

// ---------------------------------------------------------------------------
static __device__ __forceinline__ float sigm_f(float x) {
    return __frcp_rn(1.f + __expf(-x));
}
static __device__ __forceinline__ float tanh_f(float x) {
    x = fminf(fmaxf(x, -15.f), 15.f);
    float e = __expf(2.f * x);
    return (e - 1.f) / (e + 1.f);
}
static __device__ __forceinline__ void st_rel(unsigned* p, unsigned v) {
    asm volatile("st.release.gpu.u32 [%0], %1;" :: "l"(p), "r"(v) : "memory");
}
static __device__ __forceinline__ unsigned ld_acq(const unsigned* p) {
    unsigned v;
    asm volatile("ld.acquire.gpu.u32 %0, [%1];" : "=r"(v) : "l"(p) : "memory");
    return v;
}
static __device__ __forceinline__ void cp16(void* smem_dst, const void* gsrc) {
    unsigned s = (unsigned)__cvta_generic_to_shared(smem_dst);
    asm volatile("cp.async.cg.shared.global [%0], [%1], 16;" :: "r"(s), "l"(gsrc));
}
static __device__ __forceinline__ uint32_t pkbf(__nv_bfloat16 a, __nv_bfloat16 b) {
    __nv_bfloat162 t; t.x = a; t.y = b;
    return *(uint32_t*)&t;
}

// mma.sync m16n8k16 bf16 (baseline tensor ISA; compiles for compute_103)
static __device__ __forceinline__ void mma_bf16(
    float& c0, float& c1, float& c2, float& c3,
    uint32_t a0, uint32_t a1, uint32_t a2, uint32_t a3,
    uint32_t b0, uint32_t b1) {
    asm volatile(
        "mma.sync.aligned.m16n8k16.row.col.f32.bf16.bf16.f32 "
        "{%0,%1,%2,%3}, {%4,%5,%6,%7}, {%8,%9}, {%0,%1,%2,%3};"
        : "+f"(c0), "+f"(c1), "+f"(c2), "+f"(c3)
        : "r"(a0), "r"(a1), "r"(a2), "r"(a3), "r"(b0), "r"(b1));
}

// ---------------------------------------------------------------------------
__global__ void reset_k() {
    unsigned i = blockIdx.x * 256u + threadIdx.x;
    if (i < 4096u) (&g_arrive[0][0][0][0])[i] = 0u;
}

// ---------------------------------------------------------------------------
// bf16 split conversions: x -> Abuf = [hi|hi|lo], W -> Wbuf = [Whi|Wlo|Whi]
// ---------------------------------------------------------------------------
__global__ void __launch_bounds__(256) convA(const float* __restrict__ x) {
    const int row = blockIdx.x;
    const int t   = threadIdx.x;
    float2 v = *(const float2*)(x + (size_t)row * 512 + t * 2);
    __nv_bfloat16 h0 = __float2bfloat16(v.x);
    __nv_bfloat16 h1 = __float2bfloat16(v.y);
    __nv_bfloat16 l0 = __float2bfloat16(v.x - __bfloat162float(h0));
    __nv_bfloat16 l1 = __float2bfloat16(v.y - __bfloat162float(h1));
    __nv_bfloat162 hh; hh.x = h0; hh.y = h1;
    __nv_bfloat162 ll; ll.x = l0; ll.y = l1;
    __nv_bfloat162* dst = (__nv_bfloat162*)(Abuf + (size_t)row * 1536);
    dst[t] = hh; dst[256 + t] = hh; dst[512 + t] = ll;
}
__global__ void __launch_bounds__(256) convW(
    const float* __restrict__ Wf, const float* __restrict__ Wb) {
    const int j = blockIdx.x;
    const int t = threadIdx.x;
    const float* src = (j < 1024) ? (Wf + (size_t)j * 512)
                                  : (Wb + (size_t)(j - 1024) * 512);
    float2 v = *(const float2*)(src + t * 2);
    __nv_bfloat16 h0 = __float2bfloat16(v.x);
    __nv_bfloat16 h1 = __float2bfloat16(v.y);
    __nv_bfloat16 l0 = __float2bfloat16(v.x - __bfloat162float(h0));
    __nv_bfloat16 l1 = __float2bfloat16(v.y - __bfloat162float(h1));
    __nv_bfloat162 hh; hh.x = h0; hh.y = h1;
    __nv_bfloat162 ll; ll.x = l0; ll.y = l1;
    __nv_bfloat162* dst = (__nv_bfloat162*)(Wbuf + (size_t)j * 1536);
    dst[t] = hh; dst[256 + t] = ll; dst[512 + t] = hh;
}

// ---------------------------------------------------------------------------
// Tensor-core GEMM: G[m][j] = A'[m,:] . W'[j,:], K'=1536 (proven)
// ---------------------------------------------------------------------------
static constexpr int KS = 72;

__global__ void __launch_bounds__(256, 1) gemm_mma() {
    extern __shared__ __align__(16) __nv_bfloat16 smb[];
    __nv_bfloat16* As[2] = { smb,          smb + 9216  };
    __nv_bfloat16* Ws[2] = { smb + 18432,  smb + 27648 };

    const int tid = threadIdx.x;
    const int wid = tid >> 5;
    const int lane = tid & 31;
    const int gid = lane >> 2;
    const int tig = lane & 3;
    const int wm = wid >> 2;
    const int wn = wid & 3;
    const int n0 = blockIdx.x * 128;
    const int m0 = blockIdx.y * 128;

    float acc[4][4][4];
#pragma unroll
    for (int i = 0; i < 4; i++)
#pragma unroll
        for (int j = 0; j < 4; j++)
#pragma unroll
            for (int k = 0; k < 4; k++) acc[i][j][k] = 0.f;

    auto load_stage = [&](int s, int kc) {
        const __nv_bfloat16* Ag = Abuf + (size_t)m0 * 1536 + kc * 64;
        const __nv_bfloat16* Wg = Wbuf + (size_t)n0 * 1536 + kc * 64;
#pragma unroll
        for (int i = 0; i < 4; i++) {
            int idx = tid + i * 256;
            int row = idx >> 3, seg = idx & 7;
            cp16(As[s] + row * KS + seg * 8, Ag + (size_t)row * 1536 + seg * 8);
            cp16(Ws[s] + row * KS + seg * 8, Wg + (size_t)row * 1536 + seg * 8);
        }
        asm volatile("cp.async.commit_group;");
    };

    load_stage(0, 0);

    for (int kc = 0; kc < 24; ++kc) {
        const int s = kc & 1;
        if (kc + 1 < 24) load_stage(s ^ 1, kc + 1);
        if (kc + 1 < 24) asm volatile("cp.async.wait_group 1;" ::: "memory");
        else             asm volatile("cp.async.wait_group 0;" ::: "memory");
        __syncthreads();

        const __nv_bfloat16* Ab = As[s] + (wm * 64 + gid) * KS + tig * 2;
        const __nv_bfloat16* Wb2 = Ws[s] + (wn * 32 + gid) * KS + tig * 2;

#pragma unroll
        for (int kk = 0; kk < 4; ++kk) {
            const int k0 = kk * 16;
            uint32_t a[4][4];
#pragma unroll
            for (int mt = 0; mt < 4; mt++) {
                const __nv_bfloat16* p = Ab + mt * 16 * KS + k0;
                a[mt][0] = *(const uint32_t*)(p);
                a[mt][1] = *(const uint32_t*)(p + 8 * KS);
                a[mt][2] = *(const uint32_t*)(p + 8);
                a[mt][3] = *(const uint32_t*)(p + 8 * KS + 8);
            }
            uint32_t bf[4][2];
#pragma unroll
            for (int nt = 0; nt < 4; nt++) {
                const __nv_bfloat16* p = Wb2 + nt * 8 * KS + k0;
                bf[nt][0] = *(const uint32_t*)(p);
                bf[nt][1] = *(const uint32_t*)(p + 8);
            }
#pragma unroll
            for (int mt = 0; mt < 4; mt++)
#pragma unroll
                for (int nt = 0; nt < 4; nt++)
                    mma_bf16(acc[mt][nt][0], acc[mt][nt][1],
                             acc[mt][nt][2], acc[mt][nt][3],
                             a[mt][0], a[mt][1], a[mt][2], a[mt][3],
                             bf[nt][0], bf[nt][1]);
        }
        __syncthreads();
    }

#pragma unroll
    for (int mt = 0; mt < 4; mt++) {
        int mrow = m0 + wm * 64 + mt * 16 + gid;
#pragma unroll
        for (int nt = 0; nt < 4; nt++) {
            int ncol = n0 + wn * 32 + nt * 8 + tig * 2;
            float* d0 = G_buf + (size_t)mrow * 2048 + ncol;
            float* d1 = G_buf + (size_t)(mrow + 8) * 2048 + ncol;
            *(float2*)d0 = make_float2(acc[mt][nt][0], acc[mt][nt][1]);
            *(float2*)d1 = make_float2(acc[mt][nt][2], acc[mt][nt][3]);
        }
    }
}

// ---------------------------------------------------------------------------
// Transpose G[b*1024+t][j] -> Gt[t][j][b], adding bias per j. (proven)
// ---------------------------------------------------------------------------
__global__ void __launch_bounds__(256) transp(
    const float* __restrict__ bif, const float* __restrict__ bhf,
    const float* __restrict__ bib, const float* __restrict__ bhb) {
    __shared__ float tile[64][65];
    const int t  = blockIdx.y;
    const int j0 = blockIdx.x * 64;
    const int tid = threadIdx.x;

    const int jq = (tid & 15) * 4;
    const int bb = tid >> 4;
#pragma unroll
    for (int p = 0; p < 4; p++) {
        int bi = bb + p * 16;
        float4 v = *(const float4*)(G_buf + ((size_t)(bi * 1024 + t)) * 2048 + j0 + jq);
        tile[bi][jq + 0] = v.x; tile[bi][jq + 1] = v.y;
        tile[bi][jq + 2] = v.z; tile[bi][jq + 3] = v.w;
    }
    __syncthreads();

    const int bq = (tid & 15) * 4;
    const int jj = tid >> 4;
#pragma unroll
    for (int p = 0; p < 4; p++) {
        int j = jj + p * 16;
        int jg = j0 + j;
        float bias = (jg < 1024) ? (bif[jg] + bhf[jg])
                                 : (bib[jg - 1024] + bhb[jg - 1024]);
        float4 v = make_float4(tile[bq + 0][j] + bias, tile[bq + 1][j] + bias,
                               tile[bq + 2][j] + bias, tile[bq + 3][j] + bias);
        *(float4*)(Gt_buf + ((size_t)t * 2048 + j0 + j) * 64 + bq) = v;
    }
}

// ---------------------------------------------------------------------------
// Phase 2: persistent recurrence, tensor-core inner product (R16 skeleton).
// Changes vs R16: (1) h exchanged via pre-split bf16 Hbf rows (producers
// write hi/lo; staging is a raw cp.async of contiguous 1KB rows — no per-step
// conversion); (2) per-step fence drains only the small Hbf stores: the fp32
// Hhist store (consumed only by out_tr) moves after the flag signal.
// ---------------------------------------------------------------------------
__global__ void __launch_bounds__(256, 1) recur(
    const float* __restrict__ Whf, const float* __restrict__ Whb)
{
    extern __shared__ __align__(16) char smr[];
    __nv_bfloat16* hA = (__nv_bfloat16*)smr;        // [16 b][520] (hi 0..255, lo 256..511)
    float* red = (float*)(smr + 16640);             // [8 srcwarp][8 nt][32 lane][4]

    const int cta = blockIdx.x;
    const int dir = cta >> 6;
    const int grp = cta & 63;
    const int bg  = grp >> 4;
    const int qs  = grp & 15;
    const int b0  = bg * 16;
    const int qb  = qs * 16;
    const int tid = threadIdx.x;
    const int wid = tid >> 5;
    const int lane = tid & 31;
    const int gid = lane >> 2;
    const int tig = lane & 3;

    const float* W = dir ? Whb : Whf;

    // ---- B fragments in registers (one-time) ----
    uint32_t breg[6][8][2];
#pragma unroll
    for (int j = 0; j < 6; j++) {
        int c = wid + 8 * j;            // chunk 0..47
        int s = c >> 4;                 // section: 0 hi*Whi, 1 hi*Wlo, 2 lo*Whi
        int k16 = (c & 15) << 4;
        bool useLo = (s == 1);
#pragma unroll
        for (int nt = 0; nt < 8; nt++) {
            int n = nt * 8 + gid;
            int qloc = n >> 2, g = n & 3;
            const float* wr = W + (size_t)(g * 256 + qb + qloc) * 256 + k16 + 2 * tig;
            float w0 = __ldg(wr), w1 = __ldg(wr + 1);
            float w2 = __ldg(wr + 8), w3 = __ldg(wr + 9);
            __nv_bfloat16 h0 = __float2bfloat16(w0), h1 = __float2bfloat16(w1);
            __nv_bfloat16 h2 = __float2bfloat16(w2), h3 = __float2bfloat16(w3);
            if (useLo) {
                h0 = __float2bfloat16(w0 - __bfloat162float(h0));
                h1 = __float2bfloat16(w1 - __bfloat162float(h1));
                h2 = __float2bfloat16(w2 - __bfloat162float(h2));
                h3 = __float2bfloat16(w3 - __bfloat162float(h3));
            }
            breg[j][nt][0] = pkbf(h0, h1);
            breg[j][nt][1] = pkbf(h2, h3);
        }
    }

    // This thread's gate columns (within final n-tile wid)
    const int n_my = 8 * wid + 2 * tig;
    const int qlm  = n_my >> 2;         // local q (0..15)
    const int g0   = n_my & 3;          // 0 or 2
    const bool prod = ((tig & 1) == 0);

    float cst0 = 0.f, cst1 = 0.f;
    int t = dir ? 1023 : 0;

    float pre[4];
    {
        const float* base = Gt_buf + ((size_t)t * 2048 + (size_t)dir * 1024) * 64;
        const float* p0 = base + (size_t)(g0 * 256 + qb + qlm) * 64 + b0 + gid;
        const float* p1 = base + (size_t)((g0 + 1) * 256 + qb + qlm) * 64 + b0 + gid;
        pre[0] = __ldg(p0);     pre[1] = __ldg(p1);
        pre[2] = __ldg(p0 + 8); pre[3] = __ldg(p1 + 8);
    }

    float* Hd = Hhist + (size_t)dir * 1024 * 16384;
    __nv_bfloat16* Hbd = Hbf + (size_t)dir * 1024 * 64 * 512;

    for (int step = 0; step < 1024; ++step) {
        // ---- stage h: raw copy of pre-split bf16 rows ----
        if (step == 0) {
            uint32_t* z = (uint32_t*)hA;
            for (int i = tid; i < 4160; i += 256) z[i] = 0u;
        } else {
            const int tp = dir ? (t + 1) : (t - 1);
            const int row = tid >> 4;       // 0..15 local b
            const int seg = tid & 15;
            const __nv_bfloat16* srcr = Hbd + ((size_t)tp * 64 + b0 + row) * 512;
            __nv_bfloat16* dstr = hA + row * 520;
#pragma unroll
            for (int i = 0; i < 4; i++) {
                int chunk = seg + i * 16;   // 0..63 (8 bf16 each)
                cp16(dstr + chunk * 8, srcr + chunk * 8);
            }
            asm volatile("cp.async.commit_group;");
            asm volatile("cp.async.wait_group 0;" ::: "memory");
        }
        __syncthreads();

        // ---- tensor-core gates ----
        float acc[8][4];
#pragma unroll
        for (int nt = 0; nt < 8; nt++)
#pragma unroll
            for (int k = 0; k < 4; k++) acc[nt][k] = 0.f;

#pragma unroll
        for (int j = 0; j < 6; j++) {
            int c = wid + 8 * j;
            int koff = ((c >> 4) == 2 ? 256 : 0) + ((c & 15) << 4);
            const __nv_bfloat16* pa = hA + gid * 520 + koff + 2 * tig;
            uint32_t a0 = *(const uint32_t*)(pa);
            uint32_t a1 = *(const uint32_t*)(pa + 8 * 520);
            uint32_t a2 = *(const uint32_t*)(pa + 8);
            uint32_t a3 = *(const uint32_t*)(pa + 8 * 520 + 8);
#pragma unroll
            for (int nt = 0; nt < 8; nt++)
                mma_bf16(acc[nt][0], acc[nt][1], acc[nt][2], acc[nt][3],
                         a0, a1, a2, a3, breg[j][nt][0], breg[j][nt][1]);
        }

        // ---- cross-warp reduction ----
#pragma unroll
        for (int nt = 0; nt < 8; nt++)
            *(float4*)(red + ((size_t)(wid * 8 + nt) * 32 + lane) * 4) =
                make_float4(acc[nt][0], acc[nt][1], acc[nt][2], acc[nt][3]);
        __syncthreads();

        float r0 = pre[0], r1 = pre[1], r2 = pre[2], r3 = pre[3];
#pragma unroll
        for (int sw = 0; sw < 8; sw++) {
            float4 v = *(const float4*)(red + ((size_t)(sw * 8 + wid) * 32 + lane) * 4);
            r0 += v.x; r1 += v.y; r2 += v.z; r3 += v.w;
        }

        // exchange (i,f) <-> (g,o) between paired lanes
        float o0 = __shfl_xor_sync(0xffffffffu, r0, 1);
        float o1 = __shfl_xor_sync(0xffffffffu, r1, 1);
        float o2 = __shfl_xor_sync(0xffffffffu, r2, 1);
        float o3 = __shfl_xor_sync(0xffffffffu, r3, 1);

        float h0v = 0.f, h1v = 0.f;
        if (prod) {
            float ig = sigm_f(r0), fg = sigm_f(r1);
            float gg = tanh_f(o0), og = sigm_f(o1);
            cst0 = fg * cst0 + ig * gg;
            h0v = og * tanh_f(cst0);
            ig = sigm_f(r2); fg = sigm_f(r3);
            gg = tanh_f(o2); og = sigm_f(o3);
            cst1 = fg * cst1 + ig * gg;
            h1v = og * tanh_f(cst1);

            // pre-split bf16 exchange payload (covered by the fence)
            __nv_bfloat16 hi0 = __float2bfloat16(h0v);
            __nv_bfloat16 lo0 = __float2bfloat16(h0v - __bfloat162float(hi0));
            __nv_bfloat16 hi1 = __float2bfloat16(h1v);
            __nv_bfloat16 lo1 = __float2bfloat16(h1v - __bfloat162float(hi1));
            const int qg = qb + qlm;
            __nv_bfloat16* r0p = Hbd + ((size_t)t * 64 + b0 + gid) * 512;
            __nv_bfloat16* r1p = r0p + 8 * 512;
            r0p[qg] = hi0; r0p[256 + qg] = lo0;
            r1p[qg] = hi1; r1p[256 + qg] = lo1;
        }

        if (step == 1023) {
            if (prod) {
                float* hd = Hd + (size_t)t * 16384 + (size_t)(qb + qlm) * 64 + b0 + gid;
                __stcg(hd, h0v);
                __stcg(hd + 8, h1v);
            }
            break;
        }

        // ---- arrive ----
        __threadfence();
        __syncthreads();
        if (tid == 0) st_rel(&g_arrive[dir][bg][qs][0], (unsigned)(step + 1));

        // Hidden under the wait: fp32 history store (out_tr only) + prefetch
        const int tcur = t;
        t = dir ? (1022 - step) : (step + 1);
        if (prod) {
            float* hd = Hd + (size_t)tcur * 16384 + (size_t)(qb + qlm) * 64 + b0 + gid;
            __stcg(hd, h0v);
            __stcg(hd + 8, h1v);
        }
        {
            const float* base = Gt_buf + ((size_t)t * 2048 + (size_t)dir * 1024) * 64;
            const float* p0 = base + (size_t)(g0 * 256 + qb + qlm) * 64 + b0 + gid;
            const float* p1 = base + (size_t)((g0 + 1) * 256 + qb + qlm) * 64 + b0 + gid;
            pre[0] = __ldg(p0);     pre[1] = __ldg(p1);
            pre[2] = __ldg(p0 + 8); pre[3] = __ldg(p1 + 8);
        }

        // ---- wait: warp-2 lanes 0..15 poll the group's 16 flags ----
        if (tid >= 64 && tid < 80) {
            while (ld_acq(&g_arrive[dir][bg][tid - 64][0]) <= (unsigned)step) {}
        }
        __syncthreads();
    }
}

// ---------------------------------------------------------------------------
// Final: out[b][t][dir*256+q] = Hhist[dir][t][q*64+b]
// ---------------------------------------------------------------------------
__global__ void __launch_bounds__(256) out_tr(float* __restrict__ out) {
    __shared__ float tile[64][65];
    const int q0  = blockIdx.x * 64;
    const int t   = blockIdx.y;
    const int dir = blockIdx.z;
    const int tid = threadIdx.x;

    const float* src = Hhist + ((size_t)dir * 1024 + t) * 16384;
    const int b  = tid & 63;
    const int q4 = (tid >> 6) * 16;
#pragma unroll
    for (int i = 0; i < 16; i++) {
        int qq = q4 + i;
        tile[b][qq] = src[(q0 + qq) * 64 + b];
    }
    __syncthreads();

    const int qs = (tid & 15) * 4;
    const int br = tid >> 4;
#pragma unroll
    for (int p = 0; p < 4; p++) {
        int bb = br + p * 16;
        float4 v = make_float4(tile[bb][qs + 0], tile[bb][qs + 1],
                               tile[bb][qs + 2], tile[bb][qs + 3]);
        *(float4*)(out + ((size_t)bb * 1024 + t) * 512 + dir * 256 + q0 + qs) = v;
    }
}

// ---------------------------------------------------------------------------
extern "C" void kernel_launch(void* const* d_in, const int* in_sizes, int n_in,
                              void* d_out, int out_size) {
    const float* x   = (const float*)d_in[0];
    const float* Wif = (const float*)d_in[1];
    const float* Whf = (const float*)d_in[2];
    const float* bif = (const float*)d_in[3];
    const float* bhf = (const float*)d_in[4];
    const float* Wib = (const float*)d_in[5];
    const float* Whb = (const float*)d_in[6];
    const float* bib = (const float*)d_in[7];
    const float* bhb = (const float*)d_in[8];
    float* out = (float*)d_out;

    cudaFuncSetAttribute(recur,    cudaFuncAttributeMaxDynamicSharedMemorySize, 49536);
    cudaFuncSetAttribute(gemm_mma, cudaFuncAttributeMaxDynamicSharedMemorySize, 73728);

    reset_k<<<16, 256>>>();
    convA<<<65536, 256>>>(x);
    convW<<<2048, 256>>>(Wif, Wib);
    gemm_mma<<<dim3(16, 512), 256, 73728>>>();
    transp<<<dim3(32, 1024), 256>>>(bif, bhf, bib, bhb);
    recur<<<128, 256, 49536>>>(Whf, Whb);
    out_tr<<<dim3(4, 1024, 2), 256>>>(out);
}